// round 11
// baseline (speedup 1.0000x reference)
#include <cuda_runtime.h>
#include <cstdint>

#define NSTEPS 10
#define NB     512
#define NT     256
#define NBAR   14      // exactly NBAR barriers per run; replay-safe modular reset
#define NELEMS 262144
#define MASK52 ((1ull << 52) - 1ull)
#define CNT1   (1ull << 52)
#define WSTRIDE 76     // float4-aligned, conflict-free row stride
#define MSTRIDE 36     // float4-aligned, conflict-free row stride for M

// ---------------- device scratch ----------------
__device__ float g_C[16 * 2048];
__device__ float g_pre1[4096 * 32];
__device__ float g_accout[128 * 64];
__device__ float g_err32[32];
__device__ float g_abspart[NB];
__device__ unsigned long long g_sync[NBAR];
__device__ float g_vv[NSTEPS * 4096 * 32];   // v_s per (row, h) : 5.2MB
__device__ float g_dw[NSTEPS * 4096 * 64];   // dW per element; only special rows touched

struct Keys { unsigned k0[NSTEPS]; unsigned k1[NSTEPS]; };

// ---------------- threefry2x32 ----------------
#define TF_ROT(x, r) (((x) << (r)) | ((x) >> (32 - (r))))
__host__ __device__ __forceinline__ void tf2x32(unsigned k0, unsigned k1,
                                                unsigned x0, unsigned x1,
                                                unsigned* o0, unsigned* o1) {
  unsigned ks0 = k0, ks1 = k1, ks2 = k0 ^ k1 ^ 0x1BD11BDAu;
  x0 += ks0; x1 += ks1;
#define TF_R4(a,b,c,d) \
  x0 += x1; x1 = TF_ROT(x1,a); x1 ^= x0; \
  x0 += x1; x1 = TF_ROT(x1,b); x1 ^= x0; \
  x0 += x1; x1 = TF_ROT(x1,c); x1 ^= x0; \
  x0 += x1; x1 = TF_ROT(x1,d); x1 ^= x0;
  TF_R4(13,15,26,6)  x0 += ks1; x1 += ks2 + 1u;
  TF_R4(17,29,16,24) x0 += ks2; x1 += ks0 + 2u;
  TF_R4(13,15,26,6)  x0 += ks0; x1 += ks1 + 3u;
  TF_R4(17,29,16,24) x0 += ks1; x1 += ks2 + 4u;
  TF_R4(13,15,26,6)  x0 += ks2; x1 += ks0 + 5u;
#undef TF_R4
  *o0 = x0; *o1 = x1;
}

__device__ __forceinline__ unsigned tfxor(unsigned k0, unsigned k1, unsigned e) {
  unsigned o0, o1;
  tf2x32(k0, k1, 0u, e, &o0, &o1);
  return o0 ^ o1;
}

__device__ __forceinline__ float bits_to_normal(unsigned bits) {
  float f = __uint_as_float((bits >> 9) | 0x3f800000u) - 1.0f;
  const float lo = __uint_as_float(0xBF7FFFFFu);
  float u = fmaxf(lo, f * 2.0f + lo);
  float w = -log1pf(-u * u);
  float p;
  if (w < 5.0f) {
    w -= 2.5f;
    p = 2.81022636e-08f;
    p = fmaf(p, w, 3.43273939e-07f);
    p = fmaf(p, w, -3.5233877e-06f);
    p = fmaf(p, w, -4.39150654e-06f);
    p = fmaf(p, w, 0.00021858087f);
    p = fmaf(p, w, -0.00125372503f);
    p = fmaf(p, w, -0.00417768164f);
    p = fmaf(p, w, 0.246640727f);
    p = fmaf(p, w, 1.50140941f);
  } else {
    w = sqrtf(w) - 3.0f;
    p = -0.000200214257f;
    p = fmaf(p, w, 0.000100950558f);
    p = fmaf(p, w, 0.00134934322f);
    p = fmaf(p, w, -0.00367342844f);
    p = fmaf(p, w, 0.00573950773f);
    p = fmaf(p, w, -0.0076224613f);
    p = fmaf(p, w, 0.00943887047f);
    p = fmaf(p, w, 1.00167406f);
    p = fmaf(p, w, 2.83297682f);
  }
  return 1.41421356237f * (p * u);
}

__device__ __forceinline__ float wred(float v) {
#pragma unroll
  for (int o = 16; o; o >>= 1) v += __shfl_xor_sync(0xffffffffu, v, o);
  return v;
}

__device__ __forceinline__ unsigned long long arrive_poll(int k, unsigned long long payload) {
  unsigned long long add = payload + CNT1;
  unsigned long long old = atomicAdd(&g_sync[k], add);
  if ((old >> 52) == (unsigned long long)(NB - 1)) {
    *((volatile unsigned long long*)&g_sync[(k + NBAR - 1) % NBAR]) = 0ull;
    return old + add;
  }
  unsigned long long v;
  do { v = *((volatile unsigned long long*)&g_sync[k]); } while ((v >> 52) < (unsigned long long)NB);
  return v;
}

// ---------------- the one fused kernel ----------------
__global__ void __launch_bounds__(NT, 4) kFused(
    const float* __restrict__ emb, const float* __restrict__ W1,
    const float* __restrict__ b1,  const float* __restrict__ W2,
    const float* __restrict__ b2,  float* __restrict__ out, Keys K) {
  __shared__ __align__(16) float sWT[32 * WSTRIDE];   // W1 tile transposed: [h][d]
  __shared__ __align__(16) union {
    float S[2048];
    float W2T[64 * WSTRIDE];                          // [c][hh] = W2[hh][c]
  } U;
  __shared__ __align__(16) float sMT[32 * MSTRIDE];   // MT[h][hh] = sum_d W2[hh][d] W1t[d][h]
  __shared__ __align__(16) float sSD[8][64];          // per-warp dW staging (noise phase)
  __shared__ __align__(16) float sH[8][32];
  __shared__ float sRed[256];
  __shared__ float sb2s[64];
  __shared__ float swts[32];
  __shared__ float sC[32];                            // c[h] = sum_d b2[d] W1t[d][h]

  const int p = blockIdx.x;
  const int tid = threadIdx.x;
  const int lane = tid & 31, w = tid >> 5;
  const int t = p & 127;

  for (int i = tid; i < 2048; i += NT)
    sWT[(i & 31) * WSTRIDE + (i >> 5)] = W1[t * 2048 + i];
  if (tid < 64) sb2s[tid] = b2[tid];
  if (tid < 32) swts[tid] = W1[262144 + tid];

  // ---- P0: chunk sums ----
  if (p < 16) {
    for (int qq = tid; qq < 2048; qq += NT) {
      float s = 0.0f;
#pragma unroll
      for (int r = 0; r < 8; ++r) s += W1[(p * 8 + r) * 2048 + qq];
      __stcg(&g_C[p * 2048 + qq], s);
    }
    __threadfence();
  }
  __syncthreads();
  if (tid == 0) { arrive_poll(0, 0ull); }
  __syncthreads();
  __threadfence();

  // ---- P1: suffix sums + pre1 rows ----
  if (p < 128) {
    const int j = p, cj = j >> 3;
    for (int qq = tid; qq < 2048; qq += NT) {
      float s = 0.0f;
      for (int c = cj + 1; c < 16; ++c) s += __ldcg(&g_C[c * 2048 + qq]);
      for (int tt = j + 1; tt < cj * 8 + 8; ++tt) s += W1[tt * 2048 + qq];
      U.S[qq] = s;
    }
    __syncthreads();
    const int o = tid * 4;
    const int b = o >> 5, hh = o & 31;
    float v0 = b1[hh], v1 = b1[hh + 1], v2 = b1[hh + 2], v3 = b1[hh + 3];
    const float* er = emb + b * 8192 + j * 64;
#pragma unroll 8
    for (int d = 0; d < 64; ++d) {
      float ev = er[d];
      const float* spx = &U.S[d * 32 + hh];
      v0 = fmaf(ev, spx[0], v0); v1 = fmaf(ev, spx[1], v1);
      v2 = fmaf(ev, spx[2], v2); v3 = fmaf(ev, spx[3], v3);
    }
    float* pp = &g_pre1[(j * 32 + b) * 32 + hh];
    pp[0] = v0; pp[1] = v1; pp[2] = v2; pp[3] = v3;
    __threadfence();
  }
  __syncthreads();
  if (tid == 0) { arrive_poll(1, 0ull); }
  __syncthreads();
  __threadfence();

  // W2 transposed (overlays U.S after barrier 1)
  for (int i = tid; i < 2048; i += NT)
    U.W2T[(i & 63) * WSTRIDE + (i >> 6)] = W2[i];
  __syncthreads();

  // ---- row ownership ----
  const int m = (p >> 7) * 8 + w;
  const int n = t + 128 * m;
  const int b = n & 31;
  const bool sp = (n == 1024 * (b & 3) + 33 * b);
  const bool fg = ((n & 31) == (n >> 7));
  const bool spfg = sp || fg;
  const float sdt = 0.316227766016838f;
  const unsigned e0 = (unsigned)(n * 64 + lane), e1 = e0 + 32;

  const float4* wtRow = (const float4*)&sWT[lane * WSTRIDE];
  const float4* dwV = (const float4*)&sSD[w][0];

  // ---- NOISE PHASE (barrier-free): dW_s and v_s = dW_s . W1row for all steps ----
#pragma unroll 1
  for (int s = 0; s < NSTEPS; ++s) {
    const unsigned k0 = K.k0[s], k1 = K.k1[s];
    const float dW0 = bits_to_normal(tfxor(k0, k1, e0)) * sdt;
    const float dW1 = bits_to_normal(tfxor(k0, k1, e1)) * sdt;
    sSD[w][lane] = dW0;
    sSD[w][32 + lane] = dW1;
    __syncwarp();
    float v0 = 0.f, v1 = 0.f, v2 = 0.f, v3 = 0.f;
#pragma unroll
    for (int k = 0; k < 16; ++k) {
      const float4 dv = dwV[k];
      const float4 wv = wtRow[k];
      v0 = fmaf(dv.x, wv.x, v0); v1 = fmaf(dv.y, wv.y, v1);
      v2 = fmaf(dv.z, wv.z, v2); v3 = fmaf(dv.w, wv.w, v3);
    }
    __syncwarp();
    __stcg(&g_vv[s * 131072 + n * 32 + lane], (v0 + v1) + (v2 + v3));
    if (spfg) {
      __stcg(&g_dw[s * 262144 + n * 64 + lane], dW0);
      __stcg(&g_dw[s * 262144 + n * 64 + 32 + lane], dW1);
    }
  }

  // ---- M_t = W2 . W1_t (32x32) and c_t = b2 . W1_t ----
  for (int idx = tid; idx < 1024; idx += NT) {
    const int h = idx & 31, hh = idx >> 5;
    float acc = 0.f;
#pragma unroll 8
    for (int d = 0; d < 64; ++d)
      acc = fmaf(U.W2T[d * WSTRIDE + hh], sWT[h * WSTRIDE + d], acc);
    sMT[h * MSTRIDE + hh] = acc;
  }
  if (tid < 32) {
    float acc = 0.f;
#pragma unroll 8
    for (int d = 0; d < 64; ++d) acc = fmaf(sb2s[d], sWT[tid * WSTRIDE + d], acc);
    sC[tid] = acc;
  }
  __syncthreads();

  // ---- step loop ----
  float P = __ldcg(&g_pre1[n * 32 + lane]);
  float a0 = 0.f, a1 = 0.f, err = 0.f;
  const float wt = swts[lane];
  const float b2a = sb2s[lane], b2b = sb2s[32 + lane];
  const float cc = 0.05f * sC[lane];

  const float4* w2Row0 = (const float4*)&U.W2T[lane * WSTRIDE];
  const float4* w2Row1 = (const float4*)&U.W2T[(32 + lane) * WSTRIDE];
  const float4* mtRow = (const float4*)&sMT[lane * MSTRIDE];
  const float4* hV = (const float4*)&sH[w][0];

  for (int s = 0; s < NSTEPS; ++s) {
    // prefetch step-invariant data (consumed after poll)
    const float vv = __ldcg(&g_vv[s * 131072 + n * 32 + lane]);
    float dw0 = 0.f, dw1 = 0.f;
    if (spfg) {
      dw0 = __ldcg(&g_dw[s * 262144 + n * 64 + lane]);
      dw1 = __ldcg(&g_dw[s * 262144 + n * 64 + 32 + lane]);
    }

    const float h = fmaxf(P + ((float)s * 0.1f) * wt, 0.0f);
    sH[w][lane] = h;
    __syncwarp();

    // score (64 FMA) and u = h.M (32 FMA)
    float p0 = 0.f, q0 = 0.f, p1 = 0.f, q1 = 0.f;
    float u0 = 0.f, u1 = 0.f;
#pragma unroll
    for (int k = 0; k < 8; ++k) {
      const float4 hv = hV[k];
      const float4 wa = w2Row0[k];
      const float4 wb = w2Row1[k];
      const float4 mv = mtRow[k];
      p0 = fmaf(hv.x, wa.x, p0); q0 = fmaf(hv.y, wa.y, q0);
      p0 = fmaf(hv.z, wa.z, p0); q0 = fmaf(hv.w, wa.w, q0);
      p1 = fmaf(hv.x, wb.x, p1); q1 = fmaf(hv.y, wb.y, q1);
      p1 = fmaf(hv.z, wb.z, p1); q1 = fmaf(hv.w, wb.w, q1);
      u0 = fmaf(hv.x, mv.x, u0); u1 = fmaf(hv.y, mv.y, u1);
      u0 = fmaf(hv.z, mv.z, u0); u1 = fmaf(hv.w, mv.w, u1);
    }
    const float s0 = b2a + (p0 + q0);
    const float s1 = b2b + (p1 + q1);
    const float u = u0 + u1;

    // rowsq -> non-blocking arrive
    float rq = wred(fmaf(s0, s0, s1 * s1));
    if (lane == 0) sRed[w] = rq;
    __syncthreads();
    unsigned long long myv = 0;
    if (tid == 0) {
      float bp = ((sRed[0] + sRed[1]) + (sRed[2] + sRed[3])) +
                 ((sRed[4] + sRed[5]) + (sRed[6] + sRed[7]));
      unsigned long long add = ((unsigned long long)(bp * 4294967296.0f)) + CNT1;
      myv = atomicAdd(&g_sync[2 + s], add) + add;
      unsigned long long v;
      if ((myv >> 52) == (unsigned long long)NB) {
        *((volatile unsigned long long*)&g_sync[(2 + s + NBAR - 1) % NBAR]) = 0ull;
        v = myv;
      } else {
        do { v = *((volatile unsigned long long*)&g_sync[2 + s]); }
        while ((v >> 52) < (unsigned long long)NB);
      }
      sRed[0] = (float)((double)(v & MASK52) * (1.0 / 4294967296.0));
    }
    __syncthreads();
    const float snorm = sqrtf(sRed[0]);

    P += 0.05f * u + cc + snorm * vv;
    if (spfg) {
      a0 += 0.05f * s0 + snorm * dw0;
      a1 += 0.05f * s1 + snorm * dw1;
      if (sp) {
        float sq = wred(fmaf(a0, a0, a1 * a1));
        if (lane == 0) err += sq * (1.0f / 64.0f);
      }
    }
  }

  // publish outputs
  if (sp && lane == 0) __stcg(&g_err32[b], err);
  if (fg) {
    __stcg(&g_accout[(n >> 5) * 64 + lane], a0);
    __stcg(&g_accout[(n >> 5) * 64 + 32 + lane], a1);
  }
  __threadfence();
  __syncthreads();
  if (tid == 0) { arrive_poll(12, 0ull); }
  __syncthreads();
  __threadfence();

  // ---- finale sweep ----
  {
    const int base = p * 512 + tid * 2;
    const int bb = base >> 13;
    const int ii = (base >> 6) & 127;
    const int jj = ii >> 2;
    const bool he = ii < 32 * (ii & 3) + bb;
    const bool ha = (jj == bb);
    float loc = 0.0f;
#pragma unroll
    for (int q = 0; q < 2; ++q) {
      const int d = (base & 63) + q;
      float v = 0.0f;
      if (he) v = emb[jj * 8192 + ii * 64 + d];
      if (ha) v += __ldcg(&g_accout[ii * 64 + d]);
      out[base + q] = v;
      loc += fabsf(emb[base + q] - v);
    }
    loc = wred(loc);
    if (lane == 0) sRed[w] = loc;
    __syncthreads();
    if (tid == 0) {
      float bp = ((sRed[0] + sRed[1]) + (sRed[2] + sRed[3])) +
                 ((sRed[4] + sRed[5]) + (sRed[6] + sRed[7]));
      __stcg(&g_abspart[p], bp);
      __threadfence();
      arrive_poll(13, 0ull);
    }
    __syncthreads();
  }

  // block 0: final scalars
  if (p == 0) {
    __threadfence();
    sRed[tid] = __ldcg(&g_abspart[tid]) + __ldcg(&g_abspart[tid + 256]);
    __syncthreads();
    for (int off = 128; off; off >>= 1) {
      if (tid < off) sRed[tid] += sRed[tid + off];
      __syncthreads();
    }
    float sl = 0.0f;
    if (tid < 32) sl = wred(__ldcg(&g_err32[tid]));
    if (tid == 0) {
      out[NELEMS] = sl;
      out[NELEMS + 1] = sRed[0] * (1.0f / 262144.0f);
    }
  }
}

// ---------------- launch ----------------
extern "C" void kernel_launch(void* const* d_in, const int* in_sizes, int n_in,
                              void* d_out, int out_size) {
  const float* emb = (const float*)d_in[0];
  const float* W1  = (const float*)d_in[1];
  const float* b1  = (const float*)d_in[2];
  const float* W2  = (const float*)d_in[3];
  const float* b2  = (const float*)d_in[4];
  float* out = (float*)d_out;

  Keys K;
  for (int i = 0; i < NSTEPS; ++i)
    tf2x32(0u, 42u, 0u, (unsigned)i, &K.k0[i], &K.k1[i]);

  kFused<<<NB, NT>>>(emb, W1, b1, W2, b2, out, K);
}

// round 12
// speedup vs baseline: 1.1163x; 1.1163x over previous
#include <cuda_runtime.h>
#include <cstdint>

#define NSTEPS 10
#define NB     512
#define NT     256
#define NBAR   13      // slots: 0 (128-cnt), 1, 2..11 steps, 12 final; reset slot k-1 at k
#define NELEMS 262144
#define MASK52 ((1ull << 52) - 1ull)
#define CNT1   (1ull << 52)
#define WSTRIDE 76
#define MSTRIDE 36

// ---------------- device scratch ----------------
__device__ float g_C[16 * 2048];
__device__ float g_pre1[4096 * 32];
__device__ float g_err32[32];
__device__ float g_fgabs[128];
__device__ unsigned long long g_sync[NBAR];

struct Keys { unsigned k0[NSTEPS]; unsigned k1[NSTEPS]; };

// ---------------- threefry2x32 ----------------
#define TF_ROT(x, r) (((x) << (r)) | ((x) >> (32 - (r))))
__host__ __device__ __forceinline__ void tf2x32(unsigned k0, unsigned k1,
                                                unsigned x0, unsigned x1,
                                                unsigned* o0, unsigned* o1) {
  unsigned ks0 = k0, ks1 = k1, ks2 = k0 ^ k1 ^ 0x1BD11BDAu;
  x0 += ks0; x1 += ks1;
#define TF_R4(a,b,c,d) \
  x0 += x1; x1 = TF_ROT(x1,a); x1 ^= x0; \
  x0 += x1; x1 = TF_ROT(x1,b); x1 ^= x0; \
  x0 += x1; x1 = TF_ROT(x1,c); x1 ^= x0; \
  x0 += x1; x1 = TF_ROT(x1,d); x1 ^= x0;
  TF_R4(13,15,26,6)  x0 += ks1; x1 += ks2 + 1u;
  TF_R4(17,29,16,24) x0 += ks2; x1 += ks0 + 2u;
  TF_R4(13,15,26,6)  x0 += ks0; x1 += ks1 + 3u;
  TF_R4(17,29,16,24) x0 += ks1; x1 += ks2 + 4u;
  TF_R4(13,15,26,6)  x0 += ks2; x1 += ks0 + 5u;
#undef TF_R4
  *o0 = x0; *o1 = x1;
}

__device__ __forceinline__ unsigned tfxor(unsigned k0, unsigned k1, unsigned e) {
  unsigned o0, o1;
  tf2x32(k0, k1, 0u, e, &o0, &o1);
  return o0 ^ o1;
}

__device__ __forceinline__ float bits_to_normal(unsigned bits) {
  float f = __uint_as_float((bits >> 9) | 0x3f800000u) - 1.0f;
  const float lo = __uint_as_float(0xBF7FFFFFu);
  float u = fmaxf(lo, f * 2.0f + lo);
  float w = -log1pf(-u * u);
  float p;
  if (w < 5.0f) {
    w -= 2.5f;
    p = 2.81022636e-08f;
    p = fmaf(p, w, 3.43273939e-07f);
    p = fmaf(p, w, -3.5233877e-06f);
    p = fmaf(p, w, -4.39150654e-06f);
    p = fmaf(p, w, 0.00021858087f);
    p = fmaf(p, w, -0.00125372503f);
    p = fmaf(p, w, -0.00417768164f);
    p = fmaf(p, w, 0.246640727f);
    p = fmaf(p, w, 1.50140941f);
  } else {
    w = sqrtf(w) - 3.0f;
    p = -0.000200214257f;
    p = fmaf(p, w, 0.000100950558f);
    p = fmaf(p, w, 0.00134934322f);
    p = fmaf(p, w, -0.00367342844f);
    p = fmaf(p, w, 0.00573950773f);
    p = fmaf(p, w, -0.0076224613f);
    p = fmaf(p, w, 0.00943887047f);
    p = fmaf(p, w, 1.00167406f);
    p = fmaf(p, w, 2.83297682f);
  }
  return 1.41421356237f * (p * u);
}

__device__ __forceinline__ float wred(float v) {
#pragma unroll
  for (int o = 16; o; o >>= 1) v += __shfl_xor_sync(0xffffffffu, v, o);
  return v;
}

// arrive: add payload+count; last arriver (vs cnt) resets slot (k-1)%NBAR.
__device__ __forceinline__ unsigned long long bar_arrive(int k, unsigned long long payload,
                                                         unsigned cnt) {
  unsigned long long add = payload + CNT1;
  unsigned long long old = atomicAdd(&g_sync[k], add);
  if ((old >> 52) == (unsigned long long)(cnt - 1))
    *((volatile unsigned long long*)&g_sync[(k + NBAR - 1) % NBAR]) = 0ull;
  return old + add;
}
__device__ __forceinline__ unsigned long long bar_wait(int k, unsigned cnt) {
  unsigned long long v;
  do { v = *((volatile unsigned long long*)&g_sync[k]); } while ((v >> 52) < (unsigned long long)cnt);
  return v;
}

// ---------------- the one fused kernel ----------------
__global__ void __launch_bounds__(NT, 4) kFused(
    const float* __restrict__ emb, const float* __restrict__ W1,
    const float* __restrict__ b1,  const float* __restrict__ W2,
    const float* __restrict__ b2,  float* __restrict__ out, Keys K) {
  __shared__ __align__(16) float sWT[32 * WSTRIDE];   // W1_t transposed [h][d]
  __shared__ __align__(16) union {
    float S[2048];
    float W2T[64 * WSTRIDE];                          // [c][hh]
  } U;
  __shared__ __align__(16) float sMT[32 * MSTRIDE];   // MT[h][hh] = sum_d W2[hh][d] W1t[d][h]
  __shared__ __align__(16) float sSD[8][64];          // per-warp dW staging
  __shared__ __align__(16) float sH[8][32];
  __shared__ float sRed[256];
  __shared__ float sb2s[64];
  __shared__ float swts[32];
  __shared__ float sC[32];

  const int p = blockIdx.x;
  const int tid = threadIdx.x;
  const int lane = tid & 31, w = tid >> 5;
  const int t = p & 127;

  for (int i = tid; i < 2048; i += NT)
    sWT[(i & 31) * WSTRIDE + (i >> 5)] = W1[t * 2048 + i];
  if (tid < 64) sb2s[tid] = b2[tid];
  if (tid < 32) swts[tid] = W1[262144 + tid];

  // ---- P0 + P1 (blocks 0..127 only, 128-count barrier on slot 0) ----
  if (p < 128) {
    {  // P0: one store per thread
      const int c = p >> 3, qq = (p & 7) * 256 + tid;
      float s = 0.0f;
#pragma unroll
      for (int r = 0; r < 8; ++r) s += W1[(c * 8 + r) * 2048 + qq];
      __stcg(&g_C[c * 2048 + qq], s);
    }
    __threadfence();
    __syncthreads();
    if (tid == 0) {
      unsigned long long v = bar_arrive(0, 0ull, 128);
      if ((v >> 52) != 128ull) bar_wait(0, 128);
    }
    __syncthreads();
    __threadfence();

    // P1: suffix sums + pre1 rows for j = p
    const int j = p, cj = j >> 3;
    for (int qq = tid; qq < 2048; qq += NT) {
      float s = 0.0f;
      for (int c = cj + 1; c < 16; ++c) s += __ldcg(&g_C[c * 2048 + qq]);
      for (int tt = j + 1; tt < cj * 8 + 8; ++tt) s += W1[tt * 2048 + qq];
      U.S[qq] = s;
    }
    __syncthreads();
    const int o = tid * 4;
    const int b = o >> 5, hh = o & 31;
    float v0 = b1[hh], v1 = b1[hh + 1], v2 = b1[hh + 2], v3 = b1[hh + 3];
    const float* er = emb + b * 8192 + j * 64;
#pragma unroll 8
    for (int d = 0; d < 64; ++d) {
      float ev = er[d];
      const float* spx = &U.S[d * 32 + hh];
      v0 = fmaf(ev, spx[0], v0); v1 = fmaf(ev, spx[1], v1);
      v2 = fmaf(ev, spx[2], v2); v3 = fmaf(ev, spx[3], v3);
    }
    float* pp = &g_pre1[(j * 32 + b) * 32 + hh];
    pp[0] = v0; pp[1] = v1; pp[2] = v2; pp[3] = v3;
    __threadfence();
  }

  // ---- bulk finale sweep (step-independent; all blocks) ----
  float bulkPart;
  {
    const int base = p * 512 + tid * 2;
    const int bb = base >> 13;
    const int ii = (base >> 6) & 127;
    const int jj = ii >> 2;
    const bool ha = (jj == bb);
    float loc = 0.0f;
    if (!ha) {
      const bool he = ii < 32 * (ii & 3) + bb;
#pragma unroll
      for (int q = 0; q < 2; ++q) {
        const int d = (base & 63) + q;
        const float v = he ? emb[jj * 8192 + ii * 64 + d] : 0.0f;
        out[base + q] = v;
        loc += fabsf(emb[base + q] - v);
      }
    }
    loc = wred(loc);
    if (lane == 0) sRed[w] = loc;
    __syncthreads();
    bulkPart = ((sRed[0] + sRed[1]) + (sRed[2] + sRed[3])) +
               ((sRed[4] + sRed[5]) + (sRed[6] + sRed[7]));
  }
  __syncthreads();

  // non-blocking arrive at barrier 1 with bulk-abs payload
  unsigned long long myv1 = 0;
  if (tid == 0)
    myv1 = bar_arrive(1, (unsigned long long)(bulkPart * 4294967296.0f), NB);

  // overlap barrier 1: W2T load + M_t, c_t precompute (block-local data only)
  for (int i = tid; i < 2048; i += NT)
    U.W2T[(i & 63) * WSTRIDE + (i >> 6)] = W2[i];
  __syncthreads();
  for (int idx = tid; idx < 1024; idx += NT) {
    const int h = idx & 31, hh = idx >> 5;
    float acc = 0.f;
#pragma unroll 8
    for (int d = 0; d < 64; ++d)
      acc = fmaf(U.W2T[d * WSTRIDE + hh], sWT[h * WSTRIDE + d], acc);
    sMT[h * MSTRIDE + hh] = acc;
  }
  if (tid < 32) {
    float acc = 0.f;
#pragma unroll 8
    for (int d = 0; d < 64; ++d) acc = fmaf(sb2s[d], sWT[tid * WSTRIDE + d], acc);
    sC[tid] = acc;
  }

  // complete barrier 1
  if (tid == 0) {
    unsigned long long v = ((myv1 >> 52) == (unsigned long long)NB) ? myv1 : bar_wait(1, NB);
    sRed[0] = (float)((double)(v & MASK52) * (1.0 / 4294967296.0));
  }
  __syncthreads();
  const float bulkTotal = sRed[0];   // only block 0 uses at the end
  __threadfence();

  // ---- row ownership: n = t + 128*m ----
  const int m = (p >> 7) * 8 + w;
  const int n = t + 128 * m;
  const int b = n & 31;
  const bool sp = (n == 1024 * (b & 3) + 33 * b);
  const bool fg = ((n & 31) == (n >> 7));
  const bool spfg = sp || fg;
  const float sdt = 0.316227766016838f;

  float P = __ldcg(&g_pre1[n * 32 + lane]);
  float a0 = 0.f, a1 = 0.f, err = 0.f;
  const float wt = swts[lane];
  const float b2a = sb2s[lane], b2b = sb2s[32 + lane];
  const float cc = 0.05f * sC[lane];

  const float4* wtRow  = (const float4*)&sWT[lane * WSTRIDE];
  const float4* w2Row0 = (const float4*)&U.W2T[lane * WSTRIDE];
  const float4* w2Row1 = (const float4*)&U.W2T[(32 + lane) * WSTRIDE];
  const float4* mtRow  = (const float4*)&sMT[lane * MSTRIDE];
  const float4* hV     = (const float4*)&sH[w][0];
  const float4* dwV    = (const float4*)&sSD[w][0];

  for (int s = 0; s < NSTEPS; ++s) {
    // hidden from running pre-activation
    const float h = fmaxf(P + ((float)s * 0.1f) * wt, 0.0f);
    sH[w][lane] = h;
    __syncwarp();

    // fused pass: score (64 FMA) + u = h.M (32 FMA)
    float p0 = 0.f, q0 = 0.f, p1 = 0.f, q1 = 0.f, u0 = 0.f, u1 = 0.f;
#pragma unroll
    for (int k = 0; k < 8; ++k) {
      const float4 hv = hV[k];
      const float4 wa = w2Row0[k];
      const float4 wb = w2Row1[k];
      const float4 mv = mtRow[k];
      p0 = fmaf(hv.x, wa.x, p0); q0 = fmaf(hv.y, wa.y, q0);
      p0 = fmaf(hv.z, wa.z, p0); q0 = fmaf(hv.w, wa.w, q0);
      p1 = fmaf(hv.x, wb.x, p1); q1 = fmaf(hv.y, wb.y, q1);
      p1 = fmaf(hv.z, wb.z, p1); q1 = fmaf(hv.w, wb.w, q1);
      u0 = fmaf(hv.x, mv.x, u0); u1 = fmaf(hv.y, mv.y, u1);
      u0 = fmaf(hv.z, mv.z, u0); u1 = fmaf(hv.w, mv.w, u1);
    }
    const float s0 = b2a + (p0 + q0);
    const float s1 = b2b + (p1 + q1);
    const float u = u0 + u1;

    // rowsq -> non-blocking arrive
    float rq = wred(fmaf(s0, s0, s1 * s1));
    if (lane == 0) sRed[w] = rq;
    __syncthreads();
    unsigned long long myv = 0;
    if (tid == 0) {
      float bp = ((sRed[0] + sRed[1]) + (sRed[2] + sRed[3])) +
                 ((sRed[4] + sRed[5]) + (sRed[6] + sRed[7]));
      myv = bar_arrive(2 + s, (unsigned long long)(bp * 4294967296.0f), NB);
    }

    // HEAVY overlap: threefry noise + v = dW . W1row
    const unsigned k0 = K.k0[s], k1 = K.k1[s];
    const float dW0 = bits_to_normal(tfxor(k0, k1, (unsigned)(n * 64 + lane))) * sdt;
    const float dW1 = bits_to_normal(tfxor(k0, k1, (unsigned)(n * 64 + 32 + lane))) * sdt;
    sSD[w][lane] = dW0;
    sSD[w][32 + lane] = dW1;
    __syncwarp();
    float v0 = 0.f, v1 = 0.f, v2 = 0.f, v3 = 0.f;
#pragma unroll
    for (int k = 0; k < 16; ++k) {
      const float4 dv = dwV[k];
      const float4 wv = wtRow[k];
      v0 = fmaf(dv.x, wv.x, v0); v1 = fmaf(dv.y, wv.y, v1);
      v2 = fmaf(dv.z, wv.z, v2); v3 = fmaf(dv.w, wv.w, v3);
    }
    const float vv = (v0 + v1) + (v2 + v3);

    // complete barrier, broadcast snorm
    if (tid == 0) {
      unsigned long long v = ((myv >> 52) == (unsigned long long)NB) ? myv : bar_wait(2 + s, NB);
      sRed[0] = (float)((double)(v & MASK52) * (1.0 / 4294967296.0));
    }
    __syncthreads();
    const float snorm = sqrtf(sRed[0]);

    P += 0.05f * u + cc + snorm * vv;
    if (spfg) {
      a0 += 0.05f * s0 + snorm * dW0;
      a1 += 0.05f * s1 + snorm * dW1;
      if (sp) {
        float sq = wred(fmaf(a0, a0, a1 * a1));
        if (lane == 0) err += sq * (1.0f / 64.0f);
      }
    }
  }

  // ---- tail: special warps publish; single final barrier ----
  if (sp && lane == 0) __stcg(&g_err32[b], err);
  if (fg) {
    const int i = n >> 5;            // output row 0..127; bb2 = i>>2 == b
    const int bb2 = i >> 2;
    const bool he2 = i < 32 * (i & 3) + bb2;
    const int e0 = bb2 * 8192 + i * 64 + lane;
    const float em0 = emb[e0], em1 = emb[e0 + 32];
    const float o0 = (he2 ? em0 : 0.0f) + a0;
    const float o1 = (he2 ? em1 : 0.0f) + a1;
    out[e0] = o0;
    out[e0 + 32] = o1;
    float part = wred(fabsf(em0 - o0) + fabsf(em1 - o1));
    if (lane == 0) __stcg(&g_fgabs[i], part);
  }
  __threadfence();
  __syncthreads();
  if (tid == 0) bar_arrive(12, 0ull, NB);

  // block 0 alone finishes the two scalars
  if (p == 0) {
    if (tid == 0) bar_wait(12, NB);
    __syncthreads();
    if (tid < 32) {
      float e = __ldcg(&g_err32[tid]);
      float f = __ldcg(&g_fgabs[tid]) + __ldcg(&g_fgabs[tid + 32]) +
                __ldcg(&g_fgabs[tid + 64]) + __ldcg(&g_fgabs[tid + 96]);
      float se = wred(e);
      float sf = wred(f);
      if (tid == 0) {
        out[NELEMS] = se;                                     // step_loss
        out[NELEMS + 1] = (bulkTotal + sf) * (1.0f / 262144.0f);  // sequence_loss
      }
    }
  }
}

// ---------------- launch ----------------
extern "C" void kernel_launch(void* const* d_in, const int* in_sizes, int n_in,
                              void* d_out, int out_size) {
  const float* emb = (const float*)d_in[0];
  const float* W1  = (const float*)d_in[1];
  const float* b1  = (const float*)d_in[2];
  const float* W2  = (const float*)d_in[3];
  const float* b2  = (const float*)d_in[4];
  float* out = (float*)d_out;

  Keys K;
  for (int i = 0; i < NSTEPS; ++i)
    tf2x32(0u, 42u, 0u, (unsigned)i, &K.k0[i], &K.k1[i]);

  kFused<<<NB, NT>>>(emb, W1, b1, W2, b2, out, K);
}

// round 13
// speedup vs baseline: 1.1503x; 1.0305x over previous
#include <cuda_runtime.h>
#include <cstdint>

#define NSTEPS 10
#define NB     512
#define NT     256
#define NBAR   13      // unique slot-groups per run; block 0 zeroes ALL after final barrier
#define NSUB   16      // sub-slots per barrier, 256B apart (distinct LTS slices)
#define NELEMS 262144
#define MASK52 ((1ull << 52) - 1ull)
#define CNT1   (1ull << 52)
#define WSTRIDE 76
#define MSTRIDE 36

// ---------------- device scratch ----------------
__device__ float g_C[16 * 2048];
__device__ float g_pre1[4096 * 32];
__device__ float g_err32[32];
__device__ float g_fgabs[128];
struct SSlot { unsigned long long v; unsigned long long pad[31]; };  // 256B
__device__ SSlot g_sync[NBAR * NSUB];   // zero-init; zeroed again at end of every run

struct Keys { unsigned k0[NSTEPS]; unsigned k1[NSTEPS]; };

// ---------------- threefry2x32 ----------------
#define TF_ROT(x, r) (((x) << (r)) | ((x) >> (32 - (r))))
__host__ __device__ __forceinline__ void tf2x32(unsigned k0, unsigned k1,
                                                unsigned x0, unsigned x1,
                                                unsigned* o0, unsigned* o1) {
  unsigned ks0 = k0, ks1 = k1, ks2 = k0 ^ k1 ^ 0x1BD11BDAu;
  x0 += ks0; x1 += ks1;
#define TF_R4(a,b,c,d) \
  x0 += x1; x1 = TF_ROT(x1,a); x1 ^= x0; \
  x0 += x1; x1 = TF_ROT(x1,b); x1 ^= x0; \
  x0 += x1; x1 = TF_ROT(x1,c); x1 ^= x0; \
  x0 += x1; x1 = TF_ROT(x1,d); x1 ^= x0;
  TF_R4(13,15,26,6)  x0 += ks1; x1 += ks2 + 1u;
  TF_R4(17,29,16,24) x0 += ks2; x1 += ks0 + 2u;
  TF_R4(13,15,26,6)  x0 += ks0; x1 += ks1 + 3u;
  TF_R4(17,29,16,24) x0 += ks1; x1 += ks2 + 4u;
  TF_R4(13,15,26,6)  x0 += ks2; x1 += ks0 + 5u;
#undef TF_R4
  *o0 = x0; *o1 = x1;
}

__device__ __forceinline__ unsigned tfxor(unsigned k0, unsigned k1, unsigned e) {
  unsigned o0, o1;
  tf2x32(k0, k1, 0u, e, &o0, &o1);
  return o0 ^ o1;
}

__device__ __forceinline__ float bits_to_normal(unsigned bits) {
  float f = __uint_as_float((bits >> 9) | 0x3f800000u) - 1.0f;
  const float lo = __uint_as_float(0xBF7FFFFFu);
  float u = fmaxf(lo, f * 2.0f + lo);
  float w = -log1pf(-u * u);
  float p;
  if (w < 5.0f) {
    w -= 2.5f;
    p = 2.81022636e-08f;
    p = fmaf(p, w, 3.43273939e-07f);
    p = fmaf(p, w, -3.5233877e-06f);
    p = fmaf(p, w, -4.39150654e-06f);
    p = fmaf(p, w, 0.00021858087f);
    p = fmaf(p, w, -0.00125372503f);
    p = fmaf(p, w, -0.00417768164f);
    p = fmaf(p, w, 0.246640727f);
    p = fmaf(p, w, 1.50140941f);
  } else {
    w = sqrtf(w) - 3.0f;
    p = -0.000200214257f;
    p = fmaf(p, w, 0.000100950558f);
    p = fmaf(p, w, 0.00134934322f);
    p = fmaf(p, w, -0.00367342844f);
    p = fmaf(p, w, 0.00573950773f);
    p = fmaf(p, w, -0.0076224613f);
    p = fmaf(p, w, 0.00943887047f);
    p = fmaf(p, w, 1.00167406f);
    p = fmaf(p, w, 2.83297682f);
  }
  return 1.41421356237f * (p * u);
}

__device__ __forceinline__ float wred(float v) {
#pragma unroll
  for (int o = 16; o; o >>= 1) v += __shfl_xor_sync(0xffffffffu, v, o);
  return v;
}

// arrive: one atomicAdd into this block's sub-slot (16-way spread).
__device__ __forceinline__ void bar_arrive(int k, unsigned long long payload) {
  atomicAdd(&g_sync[k * NSUB + (blockIdx.x & (NSUB - 1))].v, payload + CNT1);
}
// sweep-sum all 16 sub-slots (associative fixed-point => deterministic total).
__device__ __forceinline__ unsigned long long bar_sweep(int k) {
  unsigned long long s = 0;
#pragma unroll
  for (int i = 0; i < NSUB; ++i)
    s += *((volatile unsigned long long*)&g_sync[k * NSUB + i].v);
  return s;
}
__device__ __forceinline__ unsigned long long bar_wait(int k, unsigned cnt) {
  unsigned long long s;
  do { s = bar_sweep(k); } while ((s >> 52) < (unsigned long long)cnt);
  return s;
}

// ---------------- the one fused kernel ----------------
__global__ void __launch_bounds__(NT, 4) kFused(
    const float* __restrict__ emb, const float* __restrict__ W1,
    const float* __restrict__ b1,  const float* __restrict__ W2,
    const float* __restrict__ b2,  float* __restrict__ out, Keys K) {
  __shared__ __align__(16) float sWT[32 * WSTRIDE];   // W1_t transposed [h][d]
  __shared__ __align__(16) union {
    float S[2048];
    float W2T[64 * WSTRIDE];                          // [c][hh]
  } U;
  __shared__ __align__(16) float sMT[32 * MSTRIDE];   // MT[h][hh]
  __shared__ __align__(16) float sSD[8][64];          // per-warp dW staging
  __shared__ __align__(16) float sH[8][32];
  __shared__ float sRed[256];
  __shared__ float sb2s[64];
  __shared__ float swts[32];
  __shared__ float sC[32];

  const int p = blockIdx.x;
  const int tid = threadIdx.x;
  const int lane = tid & 31, w = tid >> 5;
  const int t = p & 127;

  for (int i = tid; i < 2048; i += NT)
    sWT[(i & 31) * WSTRIDE + (i >> 5)] = W1[t * 2048 + i];
  if (tid < 64) sb2s[tid] = b2[tid];
  if (tid < 32) swts[tid] = W1[262144 + tid];

  // ---- P0 + P1 (blocks 0..127 only; 128-count barrier slot 0) ----
  if (p < 128) {
    {
      const int c = p >> 3, qq = (p & 7) * 256 + tid;
      float s = 0.0f;
#pragma unroll
      for (int r = 0; r < 8; ++r) s += W1[(c * 8 + r) * 2048 + qq];
      __stcg(&g_C[c * 2048 + qq], s);
    }
    __threadfence();
    __syncthreads();
    if (tid == 0) { bar_arrive(0, 0ull); bar_wait(0, 128); }
    __syncthreads();
    __threadfence();

    const int j = p, cj = j >> 3;
    for (int qq = tid; qq < 2048; qq += NT) {
      float s = 0.0f;
      for (int c = cj + 1; c < 16; ++c) s += __ldcg(&g_C[c * 2048 + qq]);
      for (int tt = j + 1; tt < cj * 8 + 8; ++tt) s += W1[tt * 2048 + qq];
      U.S[qq] = s;
    }
    __syncthreads();
    const int o = tid * 4;
    const int b = o >> 5, hh = o & 31;
    float v0 = b1[hh], v1 = b1[hh + 1], v2 = b1[hh + 2], v3 = b1[hh + 3];
    const float* er = emb + b * 8192 + j * 64;
#pragma unroll 8
    for (int d = 0; d < 64; ++d) {
      float ev = er[d];
      const float* spx = &U.S[d * 32 + hh];
      v0 = fmaf(ev, spx[0], v0); v1 = fmaf(ev, spx[1], v1);
      v2 = fmaf(ev, spx[2], v2); v3 = fmaf(ev, spx[3], v3);
    }
    float* pp = &g_pre1[(j * 32 + b) * 32 + hh];
    pp[0] = v0; pp[1] = v1; pp[2] = v2; pp[3] = v3;
    __threadfence();
  }

  // ---- bulk finale sweep (step-independent) ----
  float bulkPart;
  {
    const int base = p * 512 + tid * 2;
    const int bb = base >> 13;
    const int ii = (base >> 6) & 127;
    const int jj = ii >> 2;
    const bool ha = (jj == bb);
    float loc = 0.0f;
    if (!ha) {
      const bool he = ii < 32 * (ii & 3) + bb;
#pragma unroll
      for (int q = 0; q < 2; ++q) {
        const int d = (base & 63) + q;
        const float v = he ? emb[jj * 8192 + ii * 64 + d] : 0.0f;
        out[base + q] = v;
        loc += fabsf(emb[base + q] - v);
      }
    }
    loc = wred(loc);
    if (lane == 0) sRed[w] = loc;
    __syncthreads();
    bulkPart = ((sRed[0] + sRed[1]) + (sRed[2] + sRed[3])) +
               ((sRed[4] + sRed[5]) + (sRed[6] + sRed[7]));
  }
  __syncthreads();

  // non-blocking arrive at barrier 1 with bulk-abs payload
  if (tid == 0)
    bar_arrive(1, (unsigned long long)(bulkPart * 4294967296.0f));

  // overlap barrier 1: W2T load + M_t, c_t precompute
  for (int i = tid; i < 2048; i += NT)
    U.W2T[(i & 63) * WSTRIDE + (i >> 6)] = W2[i];
  __syncthreads();
  for (int idx = tid; idx < 1024; idx += NT) {
    const int h = idx & 31, hh = idx >> 5;
    float acc = 0.f;
#pragma unroll 8
    for (int d = 0; d < 64; ++d)
      acc = fmaf(U.W2T[d * WSTRIDE + hh], sWT[h * WSTRIDE + d], acc);
    sMT[h * MSTRIDE + hh] = acc;
  }
  if (tid < 32) {
    float acc = 0.f;
#pragma unroll 8
    for (int d = 0; d < 64; ++d) acc = fmaf(sb2s[d], sWT[tid * WSTRIDE + d], acc);
    sC[tid] = acc;
  }

  if (tid == 0) {
    unsigned long long v = bar_wait(1, NB);
    sRed[0] = (float)((double)(v & MASK52) * (1.0 / 4294967296.0));
  }
  __syncthreads();
  const float bulkTotal = sRed[0];
  __threadfence();

  // ---- row ownership: n = t + 128*m ----
  const int m = (p >> 7) * 8 + w;
  const int n = t + 128 * m;
  const int b = n & 31;
  const bool sp = (n == 1024 * (b & 3) + 33 * b);
  const bool fg = ((n & 31) == (n >> 7));
  const bool spfg = sp || fg;
  const float sdt = 0.316227766016838f;

  float P = __ldcg(&g_pre1[n * 32 + lane]);
  float a0 = 0.f, a1 = 0.f, err = 0.f;
  const float wt = swts[lane];
  const float b2a = sb2s[lane], b2b = sb2s[32 + lane];
  const float cc = 0.05f * sC[lane];

  const float4* wtRow  = (const float4*)&sWT[lane * WSTRIDE];
  const float4* w2Row0 = (const float4*)&U.W2T[lane * WSTRIDE];
  const float4* w2Row1 = (const float4*)&U.W2T[(32 + lane) * WSTRIDE];
  const float4* mtRow  = (const float4*)&sMT[lane * MSTRIDE];
  const float4* hV     = (const float4*)&sH[w][0];
  const float4* dwV    = (const float4*)&sSD[w][0];

  for (int s = 0; s < NSTEPS; ++s) {
    const float h = fmaxf(P + ((float)s * 0.1f) * wt, 0.0f);
    sH[w][lane] = h;
    __syncwarp();

    // fused pass: score (64 FMA) + u = h.M (32 FMA)
    float p0 = 0.f, q0 = 0.f, p1 = 0.f, q1 = 0.f, u0 = 0.f, u1 = 0.f;
#pragma unroll
    for (int k = 0; k < 8; ++k) {
      const float4 hv = hV[k];
      const float4 wa = w2Row0[k];
      const float4 wb = w2Row1[k];
      const float4 mv = mtRow[k];
      p0 = fmaf(hv.x, wa.x, p0); q0 = fmaf(hv.y, wa.y, q0);
      p0 = fmaf(hv.z, wa.z, p0); q0 = fmaf(hv.w, wa.w, q0);
      p1 = fmaf(hv.x, wb.x, p1); q1 = fmaf(hv.y, wb.y, q1);
      p1 = fmaf(hv.z, wb.z, p1); q1 = fmaf(hv.w, wb.w, q1);
      u0 = fmaf(hv.x, mv.x, u0); u1 = fmaf(hv.y, mv.y, u1);
      u0 = fmaf(hv.z, mv.z, u0); u1 = fmaf(hv.w, mv.w, u1);
    }
    const float s0 = b2a + (p0 + q0);
    const float s1 = b2b + (p1 + q1);
    const float u = u0 + u1;

    // rowsq -> non-blocking spread arrive
    float rq = wred(fmaf(s0, s0, s1 * s1));
    if (lane == 0) sRed[w] = rq;
    __syncthreads();
    if (tid == 0) {
      float bp = ((sRed[0] + sRed[1]) + (sRed[2] + sRed[3])) +
                 ((sRed[4] + sRed[5]) + (sRed[6] + sRed[7]));
      bar_arrive(2 + s, (unsigned long long)(bp * 4294967296.0f));
    }

    // HEAVY overlap: threefry noise + v = dW . W1row
    const unsigned k0 = K.k0[s], k1 = K.k1[s];
    const float dW0 = bits_to_normal(tfxor(k0, k1, (unsigned)(n * 64 + lane))) * sdt;
    const float dW1 = bits_to_normal(tfxor(k0, k1, (unsigned)(n * 64 + 32 + lane))) * sdt;
    sSD[w][lane] = dW0;
    sSD[w][32 + lane] = dW1;
    __syncwarp();
    float v0 = 0.f, v1 = 0.f, v2 = 0.f, v3 = 0.f;
#pragma unroll
    for (int k = 0; k < 16; ++k) {
      const float4 dv = dwV[k];
      const float4 wv = wtRow[k];
      v0 = fmaf(dv.x, wv.x, v0); v1 = fmaf(dv.y, wv.y, v1);
      v2 = fmaf(dv.z, wv.z, v2); v3 = fmaf(dv.w, wv.w, v3);
    }
    const float vv = (v0 + v1) + (v2 + v3);

    // poll sweep, broadcast snorm
    if (tid == 0) {
      unsigned long long v = bar_wait(2 + s, NB);
      sRed[0] = (float)((double)(v & MASK52) * (1.0 / 4294967296.0));
    }
    __syncthreads();
    const float snorm = sqrtf(sRed[0]);

    P += 0.05f * u + cc + snorm * vv;
    if (spfg) {
      a0 += 0.05f * s0 + snorm * dW0;
      a1 += 0.05f * s1 + snorm * dW1;
      if (sp) {
        float sq = wred(fmaf(a0, a0, a1 * a1));
        if (lane == 0) err += sq * (1.0f / 64.0f);
      }
    }
  }

  // ---- tail: special warps publish; single final barrier ----
  if (sp && lane == 0) __stcg(&g_err32[b], err);
  if (fg) {
    const int i = n >> 5;
    const int bb2 = i >> 2;
    const bool he2 = i < 32 * (i & 3) + bb2;
    const int e0 = bb2 * 8192 + i * 64 + lane;
    const float em0 = emb[e0], em1 = emb[e0 + 32];
    const float o0 = (he2 ? em0 : 0.0f) + a0;
    const float o1 = (he2 ? em1 : 0.0f) + a1;
    out[e0] = o0;
    out[e0 + 32] = o1;
    float part = wred(fabsf(em0 - o0) + fabsf(em1 - o1));
    if (lane == 0) __stcg(&g_fgabs[i], part);
  }
  __threadfence();
  __syncthreads();
  if (tid == 0) bar_arrive(12, 0ull);

  // block 0 alone: poll final barrier, zero ALL sync state (replay-safe), scalars
  if (p == 0) {
    if (tid == 0) bar_wait(12, NB);
    __syncthreads();
    for (int i = tid; i < NBAR * NSUB; i += NT)
      *((volatile unsigned long long*)&g_sync[i].v) = 0ull;
    if (tid < 32) {
      float e = __ldcg(&g_err32[tid]);
      float f = __ldcg(&g_fgabs[tid]) + __ldcg(&g_fgabs[tid + 32]) +
                __ldcg(&g_fgabs[tid + 64]) + __ldcg(&g_fgabs[tid + 96]);
      float se = wred(e);
      float sf = wred(f);
      if (tid == 0) {
        out[NELEMS] = se;                                         // step_loss
        out[NELEMS + 1] = (bulkTotal + sf) * (1.0f / 262144.0f);  // sequence_loss
      }
    }
  }
}

// ---------------- launch ----------------
extern "C" void kernel_launch(void* const* d_in, const int* in_sizes, int n_in,
                              void* d_out, int out_size) {
  const float* emb = (const float*)d_in[0];
  const float* W1  = (const float*)d_in[1];
  const float* b1  = (const float*)d_in[2];
  const float* W2  = (const float*)d_in[3];
  const float* b2  = (const float*)d_in[4];
  float* out = (float*)d_out;

  Keys K;
  for (int i = 0; i < NSTEPS; ++i)
    tf2x32(0u, 42u, 0u, (unsigned)i, &K.k0[i], &K.k1[i]);

  kFused<<<NB, NT>>>(emb, W1, b1, W2, b2, out, K);
}